// round 5
// baseline (speedup 1.0000x reference)
#include <cuda_runtime.h>
#include <cstdio>

#define THRESH 0.1f
#define TPB 256
#define IPT 16
#define CHUNK (TPB * IPT)     // 4096
#define MAX_SEG 256
#define MAX_BLOCKS 8192

// Scratch (no allocations allowed)
__device__ int      g_rs[MAX_SEG + 1];   // int32 copy of row_splits
__device__ unsigned g_segmin[MAX_SEG];   // segment min as float bits (scores >= 0)
__device__ int      g_minidx[MAX_SEG];   // first index achieving segment min
__device__ int      g_segcnt[MAX_SEG];   // keep count per segment
__device__ int      g_reppos[MAX_SEG];   // compacted index of first kept min
__device__ int      g_blkcnt[MAX_BLOCKS];
__device__ int      g_blkoff[MAX_BLOCKS];

__device__ __forceinline__ int find_seg(int nseg, int i) {
    int lo = 0, hi = nseg;
    while (hi - lo > 1) {
        int mid = (lo + hi) >> 1;
        if (i >= g_rs[mid]) lo = mid; else hi = mid;
    }
    return lo;
}

// Config + init: detect int64 row_splits (odd words zero), copy to int32, reset scratch.
__global__ void k_cfg(const int* __restrict__ raw, int nrs) {
    int t = threadIdx.x;
    __shared__ int is64;
    if (t == 0)
        is64 = (nrs > 2 && raw[1] == 0 && raw[2] != 0) ? 1 : 0;
    __syncthreads();
    if (t < nrs && t <= MAX_SEG) g_rs[t] = is64 ? raw[2 * t] : raw[t];
    if (t < MAX_SEG) {
        g_segmin[t] = 0x7f800000u;   // +inf bits
        g_minidx[t] = 0x7fffffff;
        g_segcnt[t] = 0;
        g_reppos[t] = 0;
    }
}

// Pass 1: per-segment min. Block covers CHUNK contiguous elements; spans <= 2 segments.
__global__ void __launch_bounds__(TPB) k_min(const float* __restrict__ sc,
                                             int n, int nseg) {
    int base = blockIdx.x * CHUNK;
    if (base >= n) return;
    int t = threadIdx.x;
    int seg0 = find_seg(nseg, base);
    int b1 = g_rs[seg0 + 1];

    unsigned m0 = 0x7f800000u, m1 = 0x7f800000u;
#pragma unroll
    for (int k = 0; k < IPT; k++) {
        int idx = base + k * TPB + t;
        if (idx < n) {
            unsigned b = __float_as_uint(sc[idx]);
            if (idx < b1) m0 = min(m0, b);
            else          m1 = min(m1, b);
        }
    }
    for (int o = 16; o > 0; o >>= 1) {
        m0 = min(m0, __shfl_down_sync(0xffffffffu, m0, o));
        m1 = min(m1, __shfl_down_sync(0xffffffffu, m1, o));
    }
    __shared__ unsigned smin[2];
    if (t < 2) smin[t] = 0x7f800000u;
    __syncthreads();
    if ((t & 31) == 0) {
        atomicMin(&smin[0], m0);
        atomicMin(&smin[1], m1);
    }
    __syncthreads();
    if (t == 0) {
        if (smin[0] != 0x7f800000u) atomicMin(&g_segmin[seg0], smin[0]);
        if (smin[1] != 0x7f800000u && seg0 + 1 < nseg)
            atomicMin(&g_segmin[seg0 + 1], smin[1]);
    }
}

// Pass 2: per-block keep count, per-segment keep counts, first-min index.
__global__ void __launch_bounds__(TPB) k_count(const float* __restrict__ sc,
                                               int n, int nseg) {
    int base = blockIdx.x * CHUNK;
    if (base >= n) return;
    int t = threadIdx.x;
    int seg0 = find_seg(nseg, base);
    int b1 = g_rs[seg0 + 1];
    unsigned min0 = g_segmin[seg0];
    unsigned min1 = (seg0 + 1 < nseg) ? g_segmin[seg0 + 1] : 0xffffffffu;

    __shared__ int smidx[2];
    if (t < 2) smidx[t] = 0x7fffffff;
    __syncthreads();

    int c0 = 0, c1 = 0;
#pragma unroll
    for (int k = 0; k < IPT; k++) {
        int idx = base + k * TPB + t;
        if (idx < n) {
            float s = sc[idx];
            unsigned b = __float_as_uint(s);
            if (idx < b1) {
                bool im = (b == min0);
                if (im) atomicMin(&smidx[0], idx);
                c0 += (int)((s > THRESH) || im);
            } else {
                bool im = (b == min1);
                if (im) atomicMin(&smidx[1], idx);
                c1 += (int)((s > THRESH) || im);
            }
        }
    }
    for (int o = 16; o > 0; o >>= 1) {
        c0 += __shfl_down_sync(0xffffffffu, c0, o);
        c1 += __shfl_down_sync(0xffffffffu, c1, o);
    }
    __shared__ int r0, r1;
    if (t == 0) { r0 = 0; r1 = 0; }
    __syncthreads();
    if ((t & 31) == 0) { atomicAdd(&r0, c0); atomicAdd(&r1, c1); }
    __syncthreads();
    if (t == 0) {
        g_blkcnt[blockIdx.x] = r0 + r1;
        if (r0) atomicAdd(&g_segcnt[seg0], r0);
        if (r1 && seg0 + 1 < nseg) atomicAdd(&g_segcnt[seg0 + 1], r1);
        if (smidx[0] != 0x7fffffff) atomicMin(&g_minidx[seg0], smidx[0]);
        if (smidx[1] != 0x7fffffff && seg0 + 1 < nseg)
            atomicMin(&g_minidx[seg0 + 1], smidx[1]);
    }
}

// Pass 3: single-block exclusive scan of block counts; optionally emit newrs (as float).
__global__ void __launch_bounds__(TPB) k_scan(int nblocks, int nseg,
                                              float* __restrict__ out,
                                              int off_nr, int osz) {
    __shared__ int wsum[TPB / 32];
    __shared__ int s_carry;
    int t = threadIdx.x, lane = t & 31, wid = t >> 5;
    if (t == 0) s_carry = 0;
    __syncthreads();
    for (int start = 0; start < nblocks; start += TPB) {
        int i = start + t;
        int v = (i < nblocks) ? g_blkcnt[i] : 0;
        int x = v;
#pragma unroll
        for (int o = 1; o < 32; o <<= 1) {
            int y = __shfl_up_sync(0xffffffffu, x, o);
            if (lane >= o) x += y;
        }
        if (lane == 31) wsum[wid] = x;
        __syncthreads();
        int wbase = 0, total = 0;
#pragma unroll
        for (int w = 0; w < TPB / 32; w++) {
            if (w < wid) wbase += wsum[w];
            total += wsum[w];
        }
        int carry = s_carry;
        if (i < nblocks) g_blkoff[i] = carry + wbase + x - v;
        __syncthreads();
        if (t == 0) s_carry = carry + total;
        __syncthreads();
    }
    if (t == 0 && off_nr >= 0 && off_nr + nseg < osz) {
        int acc = 0;
        out[off_nr] = 0.0f;
        for (int s = 0; s < nseg; s++) {
            acc += g_segcnt[s];
            out[off_nr + 1 + s] = (float)acc;
        }
    }
}

// Pass 4: rep_pos[seg] = global keep-prefix at first-min index.
__global__ void __launch_bounds__(TPB) k_reppos(const float* __restrict__ sc,
                                                int n, int nseg) {
    int seg = blockIdx.x;
    if (seg >= nseg) return;
    int t = threadIdx.x;
    int mi = g_minidx[seg];
    if (mi < 0 || mi >= n) { if (t == 0) g_reppos[seg] = 0; return; }
    int b = mi / CHUNK;
    int base = b * CHUNK;
    int segstart = g_rs[seg];
    unsigned minS = g_segmin[seg];
    unsigned minP = (seg > 0) ? g_segmin[seg - 1] : 0xffffffffu;
    int cnt = 0;
    for (int idx = base + t; idx < mi; idx += TPB) {
        float s = sc[idx];
        unsigned bb = __float_as_uint(s);
        unsigned mm = (idx >= segstart) ? minS : minP;
        cnt += (int)((s > THRESH) || (bb == mm));
    }
    for (int o = 16; o > 0; o >>= 1) cnt += __shfl_down_sync(0xffffffffu, cnt, o);
    __shared__ int r;
    if (t == 0) r = 0;
    __syncthreads();
    if ((t & 31) == 0) atomicAdd(&r, cnt);
    __syncthreads();
    if (t == 0) g_reppos[seg] = g_blkoff[b] + r;
}

// Pass 5: compaction + backgather, float32 outputs, explicit (possibly disabled) offsets.
__global__ void __launch_bounds__(TPB) k_write(const float* __restrict__ sc,
                                               int n, int nseg,
                                               float* __restrict__ out,
                                               int off_sel, int cap_sel,
                                               int off_bg, int osz) {
    int base = blockIdx.x * CHUNK;
    if (base >= n) return;
    int t = threadIdx.x;
    int start = base + t * IPT;
    int seg0 = find_seg(nseg, base);
    int b1 = g_rs[seg0 + 1];
    int segT = (start < b1) ? seg0 : seg0 + 1;
    if (segT > nseg - 1) segT = nseg - 1;
    int bT = g_rs[segT + 1];
    unsigned minT  = g_segmin[segT];
    unsigned minT1 = (segT + 1 < nseg) ? g_segmin[segT + 1] : 0xffffffffu;
    int repT  = g_reppos[segT];
    int repT1 = (segT + 1 < nseg) ? g_reppos[segT + 1] : 0;

    float v[IPT];
    if (start + IPT <= n) {
        const float4* p = reinterpret_cast<const float4*>(sc + start);
#pragma unroll
        for (int q = 0; q < IPT / 4; q++) {
            float4 f = p[q];
            v[4 * q + 0] = f.x; v[4 * q + 1] = f.y;
            v[4 * q + 2] = f.z; v[4 * q + 3] = f.w;
        }
    } else {
#pragma unroll
        for (int k = 0; k < IPT; k++) {
            int idx = start + k;
            v[k] = (idx < n) ? sc[idx] : 0.0f;
        }
    }

    unsigned mask = 0;
    int cnt = 0;
#pragma unroll
    for (int k = 0; k < IPT; k++) {
        int idx = start + k;
        if (idx < n) {
            unsigned bb = __float_as_uint(v[k]);
            bool in0 = (idx < bT);
            bool keep = (v[k] > THRESH) || (bb == (in0 ? minT : minT1));
            mask |= ((unsigned)keep) << k;
            cnt += (int)keep;
        }
    }

    int lane = t & 31, wid = t >> 5;
    int x = cnt;
#pragma unroll
    for (int o = 1; o < 32; o <<= 1) {
        int y = __shfl_up_sync(0xffffffffu, x, o);
        if (lane >= o) x += y;
    }
    __shared__ int wsum[TPB / 32];
    if (lane == 31) wsum[wid] = x;
    __syncthreads();
    int wbase = 0;
#pragma unroll
    for (int w = 0; w < TPB / 32; w++) if (w < wid) wbase += wsum[w];
    int pos = g_blkoff[blockIdx.x] + wbase + x - cnt;

#pragma unroll
    for (int k = 0; k < IPT; k++) {
        int idx = start + k;
        if (idx < n) {
            if ((mask >> k) & 1u) {
                if (off_sel >= 0 && pos < cap_sel) out[off_sel + pos] = (float)idx;
                if (off_bg >= 0 && off_bg + idx < osz) out[off_bg + idx] = (float)pos;
                pos++;
            } else {
                if (off_bg >= 0 && off_bg + idx < osz)
                    out[off_bg + idx] = (float)((idx < bT) ? repT : repT1);
            }
        }
    }
}

extern "C" void kernel_launch(void* const* d_in, const int* in_sizes, int n_in,
                              void* d_out, int out_size) {
    // Autodetect: score = largest input; row_splits = small input (2..257 elems).
    int i_sc = 0;
    for (int i = 1; i < n_in; i++) if (in_sizes[i] > in_sizes[i_sc]) i_sc = i;
    int i_rs = (i_sc == 0 && n_in > 1) ? 1 : 0;
    for (int i = 0; i < n_in; i++)
        if (i != i_sc && in_sizes[i] >= 2 && in_sizes[i] <= MAX_SEG + 1) { i_rs = i; break; }

    const float* sc    = (const float*)d_in[i_sc];
    const int*   rsraw = (const int*)d_in[i_rs];
    int n    = in_sizes[i_sc];
    int nseg = in_sizes[i_rs] - 1;
    if (nseg > MAX_SEG) nseg = MAX_SEG;
    if (nseg < 1) nseg = 1;
    int nblocks = (n + CHUNK - 1) / CHUNK;
    if (nblocks > MAX_BLOCKS) nblocks = MAX_BLOCKS;
    float* out = (float*)d_out;

    // Adaptive output layout from out_size arithmetic.
    int off_sel = -1, cap_sel = 0, off_nr = -1, off_bg = -1;
    const char* mode;
    if (out_size >= n + nseg + 1) {            // full concat [sel | newrs | backgather]
        cap_sel = out_size - n - (nseg + 1);
        off_sel = 0; off_nr = cap_sel; off_bg = cap_sel + nseg + 1;
        mode = "CONCAT";
    } else if (out_size == nseg + 1) {         // newrs only
        off_nr = 0; mode = "NEWRS";
    } else if (out_size == n) {                // backgather only
        off_bg = 0; mode = "BG";
    } else {                                   // sel only (out_size == M)
        off_sel = 0; cap_sel = out_size; mode = "SEL";
    }

    fprintf(stderr, "DIAG sizes=[%d,%d] out_size=%d mode=%s f32-out\n",
            n_in > 0 ? in_sizes[0] : -1, n_in > 1 ? in_sizes[1] : -1, out_size, mode);
    fflush(stderr);

    k_cfg<<<1, 256>>>(rsraw, nseg + 1);
    k_min<<<nblocks, TPB>>>(sc, n, nseg);
    k_count<<<nblocks, TPB>>>(sc, n, nseg);
    k_scan<<<1, TPB>>>(nblocks, nseg, out, off_nr, out_size);
    k_reppos<<<nseg, TPB>>>(sc, n, nseg);
    k_write<<<nblocks, TPB>>>(sc, n, nseg, out, off_sel, cap_sel, off_bg, out_size);
}

// round 8
// speedup vs baseline: 1.1163x; 1.1163x over previous
#include <cuda_runtime.h>
#include <cstdio>

#define THRESH 0.1f
#define TPB 256
#define IPT 16
#define CHUNK (TPB * IPT)     // 4096
#define STPB 1024
#define MAX_SEG 256
#define MAX_BLOCKS 8192
#define SENT 0xffffffffu

// Scratch (no allocations allowed)
__device__ int      g_rs[MAX_SEG + 1];
__device__ unsigned g_segmin[MAX_SEG];
__device__ int      g_reppos[MAX_SEG];
__device__ int      g_blkoff[MAX_BLOCKS];
// per-block records from pass1 (part 0 = block's first segment, part 1 = next)
__device__ int      g_bseg0[MAX_BLOCKS];
__device__ unsigned g_bmin[2][MAX_BLOCKS];
__device__ int      g_bam[2][MAX_BLOCKS];   // first index achieving part min
__device__ int      g_beq[2][MAX_BLOCKS];   // count of elements == part min
__device__ int      g_bct[2][MAX_BLOCKS];   // count of elements > THRESH

__device__ __forceinline__ int find_seg(int nseg, int i) {
    int lo = 0, hi = nseg;
    while (hi - lo > 1) {
        int mid = (lo + hi) >> 1;
        if (i >= g_rs[mid]) lo = mid; else hi = mid;
    }
    return lo;
}

// Init: detect int64 row_splits (odd words zero), copy to int32, reset scratch.
__global__ void k_cfg(const int* __restrict__ raw, int nrs) {
    int t = threadIdx.x;
    __shared__ int is64;
    if (t == 0)
        is64 = (nrs > 2 && raw[1] == 0 && raw[2] != 0) ? 1 : 0;
    __syncthreads();
    if (t < nrs && t <= MAX_SEG) g_rs[t] = is64 ? raw[2 * t] : raw[t];
    if (t < MAX_SEG) {
        g_segmin[t] = 0x7f800000u;
        g_reppos[t] = 0;
    }
}

// Pass 1 (single full read): per-block(part) min/argmin/eqcnt/threshcnt + segmin atomicMin.
__global__ void __launch_bounds__(TPB) k_pass1(const float* __restrict__ sc,
                                               int n, int nseg) {
    int b = blockIdx.x, base = b * CHUNK;
    if (base >= n) return;
    int t = threadIdx.x;
    int seg0 = find_seg(nseg, base);
    int b1 = g_rs[seg0 + 1];

    unsigned mn0 = SENT, mn1 = SENT;
    int eq0 = 0, eq1 = 0, am0 = 0x7fffffff, am1 = 0x7fffffff, ct0 = 0, ct1 = 0;
#pragma unroll
    for (int k = 0; k < IPT; k++) {
        int idx = base + k * TPB + t;      // idx increases with k -> first hit = lowest idx
        if (idx < n) {
            float s = sc[idx];
            unsigned bb = __float_as_uint(s);
            if (idx < b1) {
                ct0 += (int)(s > THRESH);
                if (bb < mn0) { mn0 = bb; eq0 = 1; am0 = idx; }
                else if (bb == mn0) eq0++;
            } else {
                ct1 += (int)(s > THRESH);
                if (bb < mn1) { mn1 = bb; eq1 = 1; am1 = idx; }
                else if (bb == mn1) eq1++;
            }
        }
    }
    // warp combine
    for (int o = 16; o > 0; o >>= 1) {
        unsigned omn0 = __shfl_down_sync(~0u, mn0, o);
        int oeq0 = __shfl_down_sync(~0u, eq0, o);
        int oam0 = __shfl_down_sync(~0u, am0, o);
        int oct0 = __shfl_down_sync(~0u, ct0, o);
        unsigned omn1 = __shfl_down_sync(~0u, mn1, o);
        int oeq1 = __shfl_down_sync(~0u, eq1, o);
        int oam1 = __shfl_down_sync(~0u, am1, o);
        int oct1 = __shfl_down_sync(~0u, ct1, o);
        ct0 += oct0; ct1 += oct1;
        if (omn0 < mn0) { mn0 = omn0; eq0 = oeq0; am0 = oam0; }
        else if (omn0 == mn0) { eq0 += oeq0; am0 = min(am0, oam0); }
        if (omn1 < mn1) { mn1 = omn1; eq1 = oeq1; am1 = oam1; }
        else if (omn1 == mn1) { eq1 += oeq1; am1 = min(am1, oam1); }
    }
    __shared__ unsigned smn[2][TPB / 32];
    __shared__ int seq_[2][TPB / 32], sam[2][TPB / 32], sct[2][TPB / 32];
    int lane = t & 31, w = t >> 5;
    if (lane == 0) {
        smn[0][w] = mn0; seq_[0][w] = eq0; sam[0][w] = am0; sct[0][w] = ct0;
        smn[1][w] = mn1; seq_[1][w] = eq1; sam[1][w] = am1; sct[1][w] = ct1;
    }
    __syncthreads();
    if (t == 0) {
#pragma unroll
        for (int p = 0; p < 2; p++) {
            unsigned M = smn[p][0]; int E = seq_[p][0], A = sam[p][0], C = sct[p][0];
            for (int i = 1; i < TPB / 32; i++) {
                C += sct[p][i];
                unsigned m = smn[p][i];
                if (m < M) { M = m; E = seq_[p][i]; A = sam[p][i]; }
                else if (m == M) { E += seq_[p][i]; A = min(A, sam[p][i]); }
            }
            g_bmin[p][b] = M; g_beq[p][b] = E; g_bam[p][b] = A; g_bct[p][b] = C;
            if (M != SENT) {
                int seg = seg0 + p;
                if (seg < nseg) atomicMin(&g_segmin[seg], M);
            }
        }
        g_bseg0[b] = seg0;
    }
}

// Pass 2 (metadata only): per-block keep counts -> exclusive scan (blkoff) + newrs.
__global__ void __launch_bounds__(STPB) k_scan2(int nblocks, int nseg,
                                                float* __restrict__ out,
                                                int off_nr, int osz) {
    __shared__ int wsum[STPB / 32];
    __shared__ int s_carry;
    __shared__ int s_segcnt[MAX_SEG];
    int t = threadIdx.x, lane = t & 31, w = t >> 5;
    for (int s = t; s < MAX_SEG; s += STPB) s_segcnt[s] = 0;
    if (t == 0) s_carry = 0;
    __syncthreads();
    for (int start = 0; start < nblocks; start += STPB) {
        int i = start + t;
        int v = 0;
        if (i < nblocks) {
            int seg0 = g_bseg0[i];
            unsigned m0 = g_bmin[0][i], m1 = g_bmin[1][i];
            int k0 = g_bct[0][i], k1 = g_bct[1][i];
            if (m0 != SENT && m0 == g_segmin[seg0] && __uint_as_float(m0) <= THRESH)
                k0 += g_beq[0][i];
            if (seg0 + 1 < nseg && m1 != SENT && m1 == g_segmin[seg0 + 1] &&
                __uint_as_float(m1) <= THRESH)
                k1 += g_beq[1][i];
            v = k0 + k1;
            if (k0) atomicAdd(&s_segcnt[seg0], k0);
            if (k1 && seg0 + 1 < nseg) atomicAdd(&s_segcnt[seg0 + 1], k1);
        }
        int x = v;
#pragma unroll
        for (int o = 1; o < 32; o <<= 1) {
            int y = __shfl_up_sync(~0u, x, o);
            if (lane >= o) x += y;
        }
        if (lane == 31) wsum[w] = x;
        __syncthreads();
        int wbase = 0, total = 0;
#pragma unroll
        for (int j = 0; j < STPB / 32; j++) {
            if (j < w) wbase += wsum[j];
            total += wsum[j];
        }
        int carry = s_carry;
        if (i < nblocks) g_blkoff[i] = carry + wbase + x - v;
        __syncthreads();
        if (t == 0) s_carry = carry + total;
        __syncthreads();
    }
    if (t == 0 && off_nr >= 0 && off_nr + nseg < osz) {
        int acc = 0;
        out[off_nr] = 0.0f;
        for (int s = 0; s < nseg; s++) { acc += s_segcnt[s]; out[off_nr + 1 + s] = (float)acc; }
    }
}

// Pass 3: per segment, locate first min index from block records, count keeps before it.
__global__ void __launch_bounds__(TPB) k_reppos(const float* __restrict__ sc,
                                                int n, int nseg, int nblocks) {
    int seg = blockIdx.x;
    if (seg >= nseg) return;
    int t = threadIdx.x;
    int segstart = g_rs[seg], segend = g_rs[seg + 1];
    if (segend <= segstart) { if (t == 0) g_reppos[seg] = 0; return; }
    unsigned sm = g_segmin[seg];
    int bs = segstart / CHUNK, be = (segend - 1) / CHUNK;
    if (be >= nblocks) be = nblocks - 1;
    int mi = 0x7fffffff;
    for (int b = bs + t; b <= be; b += TPB) {
        if (g_bseg0[b] == seg && g_bmin[0][b] == sm) mi = min(mi, g_bam[0][b]);
        if (g_bseg0[b] + 1 == seg && g_bmin[1][b] == sm) mi = min(mi, g_bam[1][b]);
    }
    for (int o = 16; o > 0; o >>= 1) mi = min(mi, __shfl_down_sync(~0u, mi, o));
    __shared__ int smi;
    if (t == 0) smi = 0x7fffffff;
    __syncthreads();
    if ((t & 31) == 0) atomicMin(&smi, mi);
    __syncthreads();
    mi = smi;
    if (mi >= n) { if (t == 0) g_reppos[seg] = 0; return; }
    int mb = mi / CHUNK, mbase = mb * CHUNK;
    unsigned minP = (seg > 0) ? g_segmin[seg - 1] : SENT;
    int cnt = 0;
    for (int idx = mbase + t; idx < mi; idx += TPB) {
        float s = sc[idx];
        unsigned bb = __float_as_uint(s);
        unsigned mm = (idx >= segstart) ? sm : minP;
        cnt += (int)((s > THRESH) || (bb == mm));
    }
    for (int o = 16; o > 0; o >>= 1) cnt += __shfl_down_sync(~0u, cnt, o);
    __shared__ int r;
    if (t == 0) r = 0;
    __syncthreads();
    if ((t & 31) == 0) atomicAdd(&r, cnt);
    __syncthreads();
    if (t == 0) g_reppos[seg] = g_blkoff[mb] + r;
}

// Pass 4: compaction + backgather, smem-staged fully coalesced stores.
__global__ void __launch_bounds__(TPB) k_write(const float* __restrict__ sc,
                                               int n, int nseg,
                                               float* __restrict__ out,
                                               int off_sel, int cap_sel,
                                               int off_bg, int osz) {
    __shared__ float s_buf[CHUNK];        // reused: sel staging, then bg staging
    __shared__ int wsum[TPB / 32];
    int b = blockIdx.x, base = b * CHUNK;
    if (base >= n) return;
    int t = threadIdx.x;
    int start = base + t * IPT;
    int seg0 = g_bseg0[b];
    int b1 = g_rs[seg0 + 1];
    int segT = (start < b1) ? seg0 : seg0 + 1;
    if (segT > nseg - 1) segT = nseg - 1;
    int bT = g_rs[segT + 1];
    unsigned minT  = g_segmin[segT];
    unsigned minT1 = (segT + 1 < nseg) ? g_segmin[segT + 1] : SENT;
    int repT  = g_reppos[segT];
    int repT1 = (segT + 1 < nseg) ? g_reppos[segT + 1] : 0;

    float v[IPT];
    if (start + IPT <= n) {
        const float4* p = reinterpret_cast<const float4*>(sc + start);
#pragma unroll
        for (int q = 0; q < IPT / 4; q++) {
            float4 f = p[q];
            v[4 * q + 0] = f.x; v[4 * q + 1] = f.y;
            v[4 * q + 2] = f.z; v[4 * q + 3] = f.w;
        }
    } else {
#pragma unroll
        for (int k = 0; k < IPT; k++) {
            int idx = start + k;
            v[k] = (idx < n) ? sc[idx] : 0.0f;
        }
    }

    unsigned mask = 0;
    int cnt = 0;
#pragma unroll
    for (int k = 0; k < IPT; k++) {
        int idx = start + k;
        if (idx < n) {
            unsigned bb = __float_as_uint(v[k]);
            bool in0 = (idx < bT);
            bool keep = (v[k] > THRESH) || (bb == (in0 ? minT : minT1));
            mask |= ((unsigned)keep) << k;
            cnt += (int)keep;
        }
    }

    int lane = t & 31, w = t >> 5;
    int x = cnt;
#pragma unroll
    for (int o = 1; o < 32; o <<= 1) {
        int y = __shfl_up_sync(~0u, x, o);
        if (lane >= o) x += y;
    }
    if (lane == 31) wsum[w] = x;
    __syncthreads();
    int wbase = 0, total = 0;
#pragma unroll
    for (int j = 0; j < TPB / 32; j++) {
        if (j < w) wbase += wsum[j];
        total += wsum[j];
    }
    int local0 = wbase + x - cnt;          // block-local exclusive prefix
    int blkoff = g_blkoff[b];

    // stage sel (block's kept range is contiguous in the output)
    {
        int p = local0;
#pragma unroll
        for (int k = 0; k < IPT; k++) {
            if ((mask >> k) & 1u) s_buf[p++] = (float)(start + k);
        }
    }
    __syncthreads();
    if (off_sel >= 0) {
        for (int j = t; j < total; j += TPB) {
            int o2 = blkoff + j;
            if (o2 < cap_sel) out[off_sel + o2] = s_buf[j];
        }
    }
    __syncthreads();

    // stage bg values in natural order, then coalesced copy
    if (off_bg >= 0) {
        int p = local0;
#pragma unroll
        for (int k = 0; k < IPT; k++) {
            int idx = start + k;
            if (idx < n) {
                if ((mask >> k) & 1u) { s_buf[t * IPT + k] = (float)(blkoff + p); p++; }
                else                  s_buf[t * IPT + k] = (float)((idx < bT) ? repT : repT1);
            }
        }
        __syncthreads();
        int lim = min(CHUNK, n - base);
        for (int j = t; j < lim; j += TPB) {
            int o2 = off_bg + base + j;
            if (o2 < osz) out[o2] = s_buf[j];
        }
    }
}

extern "C" void kernel_launch(void* const* d_in, const int* in_sizes, int n_in,
                              void* d_out, int out_size) {
    int i_sc = 0;
    for (int i = 1; i < n_in; i++) if (in_sizes[i] > in_sizes[i_sc]) i_sc = i;
    int i_rs = (i_sc == 0 && n_in > 1) ? 1 : 0;
    for (int i = 0; i < n_in; i++)
        if (i != i_sc && in_sizes[i] >= 2 && in_sizes[i] <= MAX_SEG + 1) { i_rs = i; break; }

    const float* sc    = (const float*)d_in[i_sc];
    const int*   rsraw = (const int*)d_in[i_rs];
    int n    = in_sizes[i_sc];
    int nseg = in_sizes[i_rs] - 1;
    if (nseg > MAX_SEG) nseg = MAX_SEG;
    if (nseg < 1) nseg = 1;
    int nblocks = (n + CHUNK - 1) / CHUNK;
    if (nblocks > MAX_BLOCKS) nblocks = MAX_BLOCKS;
    float* out = (float*)d_out;

    int off_sel = -1, cap_sel = 0, off_nr = -1, off_bg = -1;
    if (out_size >= n + nseg + 1) {            // [sel | newrs | backgather]
        cap_sel = out_size - n - (nseg + 1);
        off_sel = 0; off_nr = cap_sel; off_bg = cap_sel + nseg + 1;
    } else if (out_size == nseg + 1) {
        off_nr = 0;
    } else if (out_size == n) {
        off_bg = 0;
    } else {
        off_sel = 0; cap_sel = out_size;
    }

    k_cfg<<<1, 256>>>(rsraw, nseg + 1);
    k_pass1<<<nblocks, TPB>>>(sc, n, nseg);
    k_scan2<<<1, STPB>>>(nblocks, nseg, out, off_nr, out_size);
    k_reppos<<<nseg, TPB>>>(sc, n, nseg, nblocks);
    k_write<<<nblocks, TPB>>>(sc, n, nseg, out, off_sel, cap_sel, off_bg, out_size);
}

// round 10
// speedup vs baseline: 2.1456x; 1.9220x over previous
#include <cuda_runtime.h>

#define THRESH 0.1f
#define TPB 256
#define IPT 16
#define CHUNK (TPB * IPT)     // 4096
#define STPB 1024
#define MAX_SEG 256
#define MAX_BLOCKS 8192
#define SENT 0xffffffffu

// Scratch (no allocations allowed)
__device__ int      g_rs[MAX_SEG + 1];
__device__ unsigned g_segmin[MAX_SEG];
__device__ int      g_reppos[MAX_SEG];
__device__ int      g_blkoff[MAX_BLOCKS];
__device__ int      g_bseg0[MAX_BLOCKS];
__device__ unsigned g_bmin[2][MAX_BLOCKS];
__device__ int      g_bam[2][MAX_BLOCKS];    // first index achieving part min
__device__ int      g_beq[2][MAX_BLOCKS];    // count == part min
__device__ int      g_bct[2][MAX_BLOCKS];    // count > THRESH
__device__ int      g_bctb[2][MAX_BLOCKS];   // count > THRESH with idx < part argmin

__device__ __forceinline__ int find_seg(int nseg, int i) {
    int lo = 0, hi = nseg;
    while (hi - lo > 1) {
        int mid = (lo + hi) >> 1;
        if (i >= g_rs[mid]) lo = mid; else hi = mid;
    }
    return lo;
}

__global__ void k_cfg(const int* __restrict__ raw, int nrs) {
    int t = threadIdx.x;
    __shared__ int is64;
    if (t == 0)
        is64 = (nrs > 2 && raw[1] == 0 && raw[2] != 0) ? 1 : 0;
    __syncthreads();
    if (t < nrs && t <= MAX_SEG) g_rs[t] = is64 ? raw[2 * t] : raw[t];
    if (t < MAX_SEG) {
        g_segmin[t] = 0x7f800000u;
        g_reppos[t] = 0;
    }
}

// Pass 1: one full read. Per block-part: min/first-argmin/eqcnt/threshcnt/prefix-at-argmin.
__global__ void __launch_bounds__(TPB) k_pass1(const float* __restrict__ sc,
                                               int n, int nseg) {
    int b = blockIdx.x, base = b * CHUNK;
    if (base >= n) return;
    int t = threadIdx.x;
    int seg0 = find_seg(nseg, base);
    int b1 = g_rs[seg0 + 1];

    // interleaved float4 layout: element e of slot j -> idx = base + 4*(j*TPB+t) + e
    float v[IPT];
    bool full = (base + CHUNK <= n);
    if (full) {
        const float4* p = reinterpret_cast<const float4*>(sc + base);
#pragma unroll
        for (int j = 0; j < 4; j++) {
            float4 f = p[j * TPB + t];
            v[4 * j + 0] = f.x; v[4 * j + 1] = f.y;
            v[4 * j + 2] = f.z; v[4 * j + 3] = f.w;
        }
    } else {
#pragma unroll
        for (int j = 0; j < 4; j++)
#pragma unroll
            for (int e = 0; e < 4; e++) {
                int idx = base + 4 * (j * TPB + t) + e;
                v[4 * j + e] = (idx < n) ? sc[idx] : 0.0f;
            }
    }

    unsigned mn0 = SENT, mn1 = SENT;
    int eq0 = 0, eq1 = 0, am0 = 0x7fffffff, am1 = 0x7fffffff, ct0 = 0, ct1 = 0;
#pragma unroll
    for (int j = 0; j < 4; j++)
#pragma unroll
        for (int e = 0; e < 4; e++) {
            int idx = base + 4 * (j * TPB + t) + e;
            if (idx < n) {
                float s = v[4 * j + e];
                unsigned bb = __float_as_uint(s);
                if (idx < b1) {
                    ct0 += (int)(s > THRESH);
                    if (bb < mn0) { mn0 = bb; eq0 = 1; am0 = idx; }
                    else if (bb == mn0) { eq0++; am0 = min(am0, idx); }
                } else {
                    ct1 += (int)(s > THRESH);
                    if (bb < mn1) { mn1 = bb; eq1 = 1; am1 = idx; }
                    else if (bb == mn1) { eq1++; am1 = min(am1, idx); }
                }
            }
        }

    for (int o = 16; o > 0; o >>= 1) {
        unsigned omn0 = __shfl_down_sync(~0u, mn0, o);
        int oeq0 = __shfl_down_sync(~0u, eq0, o);
        int oam0 = __shfl_down_sync(~0u, am0, o);
        int oct0 = __shfl_down_sync(~0u, ct0, o);
        unsigned omn1 = __shfl_down_sync(~0u, mn1, o);
        int oeq1 = __shfl_down_sync(~0u, eq1, o);
        int oam1 = __shfl_down_sync(~0u, am1, o);
        int oct1 = __shfl_down_sync(~0u, ct1, o);
        ct0 += oct0; ct1 += oct1;
        if (omn0 < mn0) { mn0 = omn0; eq0 = oeq0; am0 = oam0; }
        else if (omn0 == mn0 && mn0 != SENT) { eq0 += oeq0; am0 = min(am0, oam0); }
        if (omn1 < mn1) { mn1 = omn1; eq1 = oeq1; am1 = oam1; }
        else if (omn1 == mn1 && mn1 != SENT) { eq1 += oeq1; am1 = min(am1, oam1); }
    }

    __shared__ unsigned smn[2][TPB / 32];
    __shared__ int seq_[2][TPB / 32], sam[2][TPB / 32], sct[2][TPB / 32];
    __shared__ int s_am[2], s_ctb[2];
    int lane = t & 31, w = t >> 5;
    if (lane == 0) {
        smn[0][w] = mn0; seq_[0][w] = eq0; sam[0][w] = am0; sct[0][w] = ct0;
        smn[1][w] = mn1; seq_[1][w] = eq1; sam[1][w] = am1; sct[1][w] = ct1;
    }
    __syncthreads();
    if (t == 0) {
#pragma unroll
        for (int p = 0; p < 2; p++) {
            unsigned M = smn[p][0]; int E = seq_[p][0], A = sam[p][0], C = sct[p][0];
            for (int i = 1; i < TPB / 32; i++) {
                C += sct[p][i];
                unsigned m = smn[p][i];
                if (m < M) { M = m; E = seq_[p][i]; A = sam[p][i]; }
                else if (m == M && M != SENT) { E += seq_[p][i]; A = min(A, sam[p][i]); }
            }
            g_bmin[p][b] = M; g_beq[p][b] = E; g_bam[p][b] = A; g_bct[p][b] = C;
            s_am[p] = A; s_ctb[p] = 0;
            if (M != SENT) {
                int seg = seg0 + p;
                if (seg < nseg) atomicMin(&g_segmin[seg], M);
            }
        }
        g_bseg0[b] = seg0;
    }
    __syncthreads();
    // prefix-at-argmin: count of (s>THRESH) with idx < argmin, within each part
    int A0 = s_am[0], A1 = s_am[1];
    int cb0 = 0, cb1 = 0;
#pragma unroll
    for (int j = 0; j < 4; j++)
#pragma unroll
        for (int e = 0; e < 4; e++) {
            int idx = base + 4 * (j * TPB + t) + e;
            if (idx < n) {
                bool thr = v[4 * j + e] > THRESH;
                if (idx < b1) cb0 += (int)(thr && idx < A0);
                else          cb1 += (int)(thr && idx < A1);
            }
        }
    for (int o = 16; o > 0; o >>= 1) {
        cb0 += __shfl_down_sync(~0u, cb0, o);
        cb1 += __shfl_down_sync(~0u, cb1, o);
    }
    if (lane == 0) {
        if (cb0) atomicAdd(&s_ctb[0], cb0);
        if (cb1) atomicAdd(&s_ctb[1], cb1);
    }
    __syncthreads();
    if (t == 0) { g_bctb[0][b] = s_ctb[0]; g_bctb[1][b] = s_ctb[1]; }
}

// Pass 2: metadata only. blkoff scan + newrs + reppos (no score reads).
__global__ void __launch_bounds__(STPB) k_scan2(int nblocks, int nseg,
                                                float* __restrict__ out,
                                                int off_nr, int osz) {
    __shared__ int wsum[STPB / 32];
    __shared__ int s_carry;
    __shared__ int s_segcnt[MAX_SEG];
    __shared__ int s_argmin[MAX_SEG];
    int t = threadIdx.x, lane = t & 31, w = t >> 5;
    for (int s = t; s < MAX_SEG; s += STPB) { s_segcnt[s] = 0; s_argmin[s] = 0x7fffffff; }
    if (t == 0) s_carry = 0;
    __syncthreads();
    for (int start = 0; start < nblocks; start += STPB) {
        int i = start + t;
        int v = 0;
        if (i < nblocks) {
            int seg0 = g_bseg0[i];
            unsigned m0 = g_bmin[0][i], m1 = g_bmin[1][i];
            int k0 = g_bct[0][i], k1 = g_bct[1][i];
            if (m0 != SENT && m0 == g_segmin[seg0] && __uint_as_float(m0) <= THRESH)
                k0 += g_beq[0][i];
            if (seg0 + 1 < nseg && m1 != SENT && m1 == g_segmin[seg0 + 1] &&
                __uint_as_float(m1) <= THRESH)
                k1 += g_beq[1][i];
            v = k0 + k1;
            if (k0) atomicAdd(&s_segcnt[seg0], k0);
            if (k1 && seg0 + 1 < nseg) atomicAdd(&s_segcnt[seg0 + 1], k1);
            if (m0 != SENT && m0 == g_segmin[seg0])
                atomicMin(&s_argmin[seg0], g_bam[0][i]);
            if (seg0 + 1 < nseg && m1 != SENT && m1 == g_segmin[seg0 + 1])
                atomicMin(&s_argmin[seg0 + 1], g_bam[1][i]);
        }
        int x = v;
#pragma unroll
        for (int o = 1; o < 32; o <<= 1) {
            int y = __shfl_up_sync(~0u, x, o);
            if (lane >= o) x += y;
        }
        if (lane == 31) wsum[w] = x;
        __syncthreads();
        int wbase = 0, total = 0;
#pragma unroll
        for (int j = 0; j < STPB / 32; j++) {
            if (j < w) wbase += wsum[j];
            total += wsum[j];
        }
        int carry = s_carry;
        if (i < nblocks) g_blkoff[i] = carry + wbase + x - v;
        __syncthreads();
        if (t == 0) s_carry = carry + total;
        __syncthreads();
    }
    // reppos: the unique (block, part) holding each segment's first argmin publishes it.
    for (int i = t; i < nblocks; i += STPB) {
        int seg0 = g_bseg0[i];
        unsigned m0 = g_bmin[0][i], m1 = g_bmin[1][i];
        if (m0 != SENT && m0 == g_segmin[seg0] && g_bam[0][i] == s_argmin[seg0])
            g_reppos[seg0] = g_blkoff[i] + g_bctb[0][i];
        if (seg0 + 1 < nseg && m1 != SENT && m1 == g_segmin[seg0 + 1] &&
            g_bam[1][i] == s_argmin[seg0 + 1]) {
            int k0 = g_bct[0][i];
            if (m0 != SENT && m0 == g_segmin[seg0] && __uint_as_float(m0) <= THRESH)
                k0 += g_beq[0][i];
            g_reppos[seg0 + 1] = g_blkoff[i] + k0 + g_bctb[1][i];
        }
    }
    if (t == 0 && off_nr >= 0 && off_nr + nseg < osz) {
        int acc = 0;
        out[off_nr] = 0.0f;
        for (int s = 0; s < nseg; s++) { acc += s_segcnt[s]; out[off_nr + 1 + s] = (float)acc; }
    }
}

// Pass 3: compaction + backgather. Interleaved float4 loads; bg staged through smem
// so the global stores are coalesced scalars (alignment-agnostic).
__global__ void __launch_bounds__(TPB) k_write(const float* __restrict__ sc,
                                               int n, int nseg,
                                               float* __restrict__ out,
                                               int off_sel, int cap_sel,
                                               int off_bg, int osz) {
    __shared__ float s_buf[CHUNK];        // 16 KB bg staging, natural order
    __shared__ int s_wt[4][TPB / 32];
    __shared__ int s_off[32];
    int b = blockIdx.x, base = b * CHUNK;
    if (base >= n) return;
    int t = threadIdx.x, lane = t & 31, w = t >> 5;
    int seg0 = g_bseg0[b];
    int b1 = g_rs[seg0 + 1];
    unsigned min0 = g_segmin[seg0];
    unsigned min1 = (seg0 + 1 < nseg) ? g_segmin[seg0 + 1] : SENT;
    int rep0 = g_reppos[seg0];
    int rep1 = (seg0 + 1 < nseg) ? g_reppos[seg0 + 1] : 0;

    bool full = (base + CHUNK <= n);
    float v[IPT];
    if (full) {
        const float4* p = reinterpret_cast<const float4*>(sc + base);
#pragma unroll
        for (int j = 0; j < 4; j++) {
            float4 f = p[j * TPB + t];
            v[4 * j + 0] = f.x; v[4 * j + 1] = f.y;
            v[4 * j + 2] = f.z; v[4 * j + 3] = f.w;
        }
    } else {
#pragma unroll
        for (int j = 0; j < 4; j++)
#pragma unroll
            for (int e = 0; e < 4; e++) {
                int idx = base + 4 * (j * TPB + t) + e;
                v[4 * j + e] = (idx < n) ? sc[idx] : 0.0f;
            }
    }

    unsigned km[4];
    int lpre[4];
#pragma unroll
    for (int j = 0; j < 4; j++) {
        unsigned m = 0;
#pragma unroll
        for (int e = 0; e < 4; e++) {
            int idx = base + 4 * (j * TPB + t) + e;
            if (idx < n) {
                float s = v[4 * j + e];
                unsigned bb = __float_as_uint(s);
                bool keep = (s > THRESH) || (bb == ((idx < b1) ? min0 : min1));
                m |= ((unsigned)keep) << e;
            }
        }
        km[j] = m;
        int c = __popc(m);
        int x = c;
#pragma unroll
        for (int o = 1; o < 32; o <<= 1) {
            int y = __shfl_up_sync(~0u, x, o);
            if (lane >= o) x += y;
        }
        lpre[j] = x - c;
        if (lane == 31) s_wt[j][w] = x;
    }
    __syncthreads();
    if (t < 32) {
        int val = s_wt[t >> 3][t & 7];    // order (j, w): l = j*8 + w
        int x = val;
#pragma unroll
        for (int o = 1; o < 32; o <<= 1) {
            int y = __shfl_up_sync(~0u, x, o);
            if ((t & 31) >= o) x += y;
        }
        s_off[t] = x - val;
    }
    __syncthreads();

    int blkoff = g_blkoff[b];
#pragma unroll
    for (int j = 0; j < 4; j++) {
        int pos0 = blkoff + s_off[j * 8 + w] + lpre[j];
        float bgv[4];
#pragma unroll
        for (int e = 0; e < 4; e++) {
            int idx = base + 4 * (j * TPB + t) + e;
            bool keep = (km[j] >> e) & 1u;
            int inner = __popc(km[j] & ((1u << e) - 1u));
            int pos = pos0 + inner;
            if (keep && off_sel >= 0 && pos < cap_sel)
                out[off_sel + pos] = (float)idx;
            bgv[e] = (float)(keep ? pos : ((idx < b1) ? rep0 : rep1));
        }
        // stage into smem in natural order (STS.128, conflict-free)
        float4* sb = reinterpret_cast<float4*>(s_buf);
        sb[j * TPB + t] = make_float4(bgv[0], bgv[1], bgv[2], bgv[3]);
    }
    __syncthreads();
    if (off_bg >= 0) {
        int lim = min(CHUNK, n - base);
        for (int i = t; i < lim; i += TPB) {
            int o2 = off_bg + base + i;
            if (o2 < osz) out[o2] = s_buf[i];
        }
    }
}

extern "C" void kernel_launch(void* const* d_in, const int* in_sizes, int n_in,
                              void* d_out, int out_size) {
    int i_sc = 0;
    for (int i = 1; i < n_in; i++) if (in_sizes[i] > in_sizes[i_sc]) i_sc = i;
    int i_rs = (i_sc == 0 && n_in > 1) ? 1 : 0;
    for (int i = 0; i < n_in; i++)
        if (i != i_sc && in_sizes[i] >= 2 && in_sizes[i] <= MAX_SEG + 1) { i_rs = i; break; }

    const float* sc    = (const float*)d_in[i_sc];
    const int*   rsraw = (const int*)d_in[i_rs];
    int n    = in_sizes[i_sc];
    int nseg = in_sizes[i_rs] - 1;
    if (nseg > MAX_SEG) nseg = MAX_SEG;
    if (nseg < 1) nseg = 1;
    int nblocks = (n + CHUNK - 1) / CHUNK;
    if (nblocks > MAX_BLOCKS) nblocks = MAX_BLOCKS;
    float* out = (float*)d_out;

    int off_sel = -1, cap_sel = 0, off_nr = -1, off_bg = -1;
    if (out_size >= n + nseg + 1) {            // [sel | newrs | backgather]
        cap_sel = out_size - n - (nseg + 1);
        off_sel = 0; off_nr = cap_sel; off_bg = cap_sel + nseg + 1;
    } else if (out_size == nseg + 1) {
        off_nr = 0;
    } else if (out_size == n) {
        off_bg = 0;
    } else {
        off_sel = 0; cap_sel = out_size;
    }

    k_cfg<<<1, 256>>>(rsraw, nseg + 1);
    k_pass1<<<nblocks, TPB>>>(sc, n, nseg);
    k_scan2<<<1, STPB>>>(nblocks, nseg, out, off_nr, out_size);
    k_write<<<nblocks, TPB>>>(sc, n, nseg, out, off_sel, cap_sel, off_bg, out_size);
}

// round 11
// speedup vs baseline: 2.5973x; 1.2105x over previous
#include <cuda_runtime.h>

#define THRESH 0.1f
#define TPB 256
#define IPT 16
#define CHUNK (TPB * IPT)     // 4096
#define STPB 1024
#define MAX_SEG 256
#define MAX_BLOCKS 8192
#define SENT 0xffffffffu
#define PADF __uint_as_float(0xffffffffu)   // -NaN: fails >THRESH, max as uint

// Scratch (no allocations allowed)
__device__ int      g_rs[MAX_SEG + 1];
__device__ unsigned g_segmin[MAX_SEG];
__device__ int      g_reppos[MAX_SEG];
__device__ int      g_blkoff[MAX_BLOCKS];
__device__ int      g_bseg0[MAX_BLOCKS];
__device__ unsigned g_bmin[2][MAX_BLOCKS];
__device__ int      g_bam[2][MAX_BLOCKS];    // first index achieving part min
__device__ int      g_beq[2][MAX_BLOCKS];    // count == part min
__device__ int      g_bct[2][MAX_BLOCKS];    // count > THRESH
__device__ int      g_bctb[2][MAX_BLOCKS];   // count > THRESH with idx < part argmin

__device__ __forceinline__ int find_seg(int nseg, int i) {
    int lo = 0, hi = nseg;
    while (hi - lo > 1) {
        int mid = (lo + hi) >> 1;
        if (i >= g_rs[mid]) lo = mid; else hi = mid;
    }
    return lo;
}

__global__ void k_cfg(const int* __restrict__ raw, int nrs) {
    int t = threadIdx.x;
    __shared__ int is64;
    if (t == 0)
        is64 = (nrs > 2 && raw[1] == 0 && raw[2] != 0) ? 1 : 0;
    __syncthreads();
    if (t < nrs && t <= MAX_SEG) g_rs[t] = is64 ? raw[2 * t] : raw[t];
    if (t < MAX_SEG) {
        g_segmin[t] = 0x7f800000u;
        g_reppos[t] = 0;
    }
}

// Load CHUNK as interleaved float4: elem e of slot j -> idx = base + 4*(j*TPB+t) + e.
// Tail elements padded with -NaN bits.
__device__ __forceinline__ void load_chunk(const float* __restrict__ sc,
                                           int base, int n, int t, float* v, bool full) {
    if (full) {
        const float4* p = reinterpret_cast<const float4*>(sc + base);
#pragma unroll
        for (int j = 0; j < 4; j++) {
            float4 f = p[j * TPB + t];
            v[4 * j + 0] = f.x; v[4 * j + 1] = f.y;
            v[4 * j + 2] = f.z; v[4 * j + 3] = f.w;
        }
    } else {
#pragma unroll
        for (int j = 0; j < 4; j++)
#pragma unroll
            for (int e = 0; e < 4; e++) {
                int idx = base + 4 * (j * TPB + t) + e;
                v[4 * j + e] = (idx < n) ? sc[idx] : PADF;
            }
    }
}

// Pass 1: one full read; per block-part min/argmin/eqcnt/threshcnt/prefix-at-argmin.
__global__ void __launch_bounds__(TPB) k_pass1(const float* __restrict__ sc,
                                               int n, int nseg) {
    int b = blockIdx.x, base = b * CHUNK;
    if (base >= n) return;
    int t = threadIdx.x, lane = t & 31, w = t >> 5;
    int seg0 = find_seg(nseg, base);
    int b1 = g_rs[seg0 + 1];
    bool full = (base + CHUNK <= n);
    bool oneseg = (b1 >= base + CHUNK) || (b1 >= n);

    float v[IPT];
    load_chunk(sc, base, n, t, v, full);

    if (oneseg) {
        // ---- fast path: single segment ----
        unsigned mn = SENT; int ct = 0;
#pragma unroll
        for (int k = 0; k < IPT; k++) {
            mn = min(mn, __float_as_uint(v[k]));
            ct += (int)(v[k] > THRESH);
        }
        for (int o = 16; o > 0; o >>= 1) {
            mn = min(mn, __shfl_down_sync(~0u, mn, o));
            ct += __shfl_down_sync(~0u, ct, o);
        }
        __shared__ unsigned smn[TPB / 32];
        __shared__ int sct[TPB / 32];
        __shared__ unsigned sM;
        __shared__ int sCt, sEq, sAm, sCtb;
        if (lane == 0) { smn[w] = mn; sct[w] = ct; }
        __syncthreads();
        if (t == 0) {
            unsigned M = smn[0]; int C = sct[0];
#pragma unroll
            for (int i = 1; i < TPB / 32; i++) { M = min(M, smn[i]); C += sct[i]; }
            sM = M; sCt = C; sEq = 0; sAm = 0x7fffffff; sCtb = 0;
        }
        __syncthreads();
        unsigned M = sM;
        int eq = 0, am = 0x7fffffff;
#pragma unroll
        for (int j = 0; j < 4; j++)
#pragma unroll
            for (int e = 0; e < 4; e++) {
                if (__float_as_uint(v[4 * j + e]) == M) {
                    eq++;
                    am = min(am, base + 4 * (j * TPB + t) + e);
                }
            }
        for (int o = 16; o > 0; o >>= 1) {
            eq += __shfl_down_sync(~0u, eq, o);
            am = min(am, __shfl_down_sync(~0u, am, o));
        }
        if (lane == 0 && eq) { atomicAdd(&sEq, eq); atomicMin(&sAm, am); }
        __syncthreads();
        int A = sAm;
        int cb = 0;
#pragma unroll
        for (int j = 0; j < 4; j++)
#pragma unroll
            for (int e = 0; e < 4; e++) {
                int idx = base + 4 * (j * TPB + t) + e;
                cb += (int)((v[4 * j + e] > THRESH) && idx < A);
            }
        for (int o = 16; o > 0; o >>= 1) cb += __shfl_down_sync(~0u, cb, o);
        if (lane == 0 && cb) atomicAdd(&sCtb, cb);
        __syncthreads();
        if (t == 0) {
            g_bmin[0][b] = M; g_beq[0][b] = sEq; g_bam[0][b] = sAm;
            g_bct[0][b] = sCt; g_bctb[0][b] = sCtb;
            g_bmin[1][b] = SENT; g_beq[1][b] = 0; g_bam[1][b] = 0x7fffffff;
            g_bct[1][b] = 0; g_bctb[1][b] = 0;
            g_bseg0[b] = seg0;
            atomicMin(&g_segmin[seg0], M);
        }
        return;
    }

    // ---- slow path: block straddles a segment boundary (rare) ----
    unsigned mn0 = SENT, mn1 = SENT;
    int eq0 = 0, eq1 = 0, am0 = 0x7fffffff, am1 = 0x7fffffff, ct0 = 0, ct1 = 0;
#pragma unroll
    for (int j = 0; j < 4; j++)
#pragma unroll
        for (int e = 0; e < 4; e++) {
            int idx = base + 4 * (j * TPB + t) + e;
            float s = v[4 * j + e];
            unsigned bb = __float_as_uint(s);
            if (idx < b1) {
                ct0 += (int)(s > THRESH);
                if (bb < mn0) { mn0 = bb; eq0 = 1; am0 = idx; }
                else if (bb == mn0) { eq0++; am0 = min(am0, idx); }
            } else {
                ct1 += (int)(s > THRESH);
                if (bb < mn1) { mn1 = bb; eq1 = 1; am1 = idx; }
                else if (bb == mn1) { eq1++; am1 = min(am1, idx); }
            }
        }
    for (int o = 16; o > 0; o >>= 1) {
        unsigned omn0 = __shfl_down_sync(~0u, mn0, o);
        int oeq0 = __shfl_down_sync(~0u, eq0, o);
        int oam0 = __shfl_down_sync(~0u, am0, o);
        int oct0 = __shfl_down_sync(~0u, ct0, o);
        unsigned omn1 = __shfl_down_sync(~0u, mn1, o);
        int oeq1 = __shfl_down_sync(~0u, eq1, o);
        int oam1 = __shfl_down_sync(~0u, am1, o);
        int oct1 = __shfl_down_sync(~0u, ct1, o);
        ct0 += oct0; ct1 += oct1;
        if (omn0 < mn0) { mn0 = omn0; eq0 = oeq0; am0 = oam0; }
        else if (omn0 == mn0 && mn0 != SENT) { eq0 += oeq0; am0 = min(am0, oam0); }
        if (omn1 < mn1) { mn1 = omn1; eq1 = oeq1; am1 = oam1; }
        else if (omn1 == mn1 && mn1 != SENT) { eq1 += oeq1; am1 = min(am1, oam1); }
    }
    __shared__ unsigned smn2[2][TPB / 32];
    __shared__ int seq2[2][TPB / 32], sam2[2][TPB / 32], sct2[2][TPB / 32];
    __shared__ int s_am2[2], s_ctb2[2];
    if (lane == 0) {
        smn2[0][w] = mn0; seq2[0][w] = eq0; sam2[0][w] = am0; sct2[0][w] = ct0;
        smn2[1][w] = mn1; seq2[1][w] = eq1; sam2[1][w] = am1; sct2[1][w] = ct1;
    }
    __syncthreads();
    if (t == 0) {
#pragma unroll
        for (int p = 0; p < 2; p++) {
            unsigned M = smn2[p][0]; int E = seq2[p][0], A = sam2[p][0], C = sct2[p][0];
            for (int i = 1; i < TPB / 32; i++) {
                C += sct2[p][i];
                unsigned m = smn2[p][i];
                if (m < M) { M = m; E = seq2[p][i]; A = sam2[p][i]; }
                else if (m == M && M != SENT) { E += seq2[p][i]; A = min(A, sam2[p][i]); }
            }
            g_bmin[p][b] = M; g_beq[p][b] = E; g_bam[p][b] = A; g_bct[p][b] = C;
            s_am2[p] = A; s_ctb2[p] = 0;
            if (M != SENT) {
                int seg = seg0 + p;
                if (seg < nseg) atomicMin(&g_segmin[seg], M);
            }
        }
        g_bseg0[b] = seg0;
    }
    __syncthreads();
    int A0 = s_am2[0], A1 = s_am2[1];
    int cb0 = 0, cb1 = 0;
#pragma unroll
    for (int j = 0; j < 4; j++)
#pragma unroll
        for (int e = 0; e < 4; e++) {
            int idx = base + 4 * (j * TPB + t) + e;
            bool thr = v[4 * j + e] > THRESH;
            if (idx < b1) cb0 += (int)(thr && idx < A0);
            else          cb1 += (int)(thr && idx < A1);
        }
    for (int o = 16; o > 0; o >>= 1) {
        cb0 += __shfl_down_sync(~0u, cb0, o);
        cb1 += __shfl_down_sync(~0u, cb1, o);
    }
    if (lane == 0) {
        if (cb0) atomicAdd(&s_ctb2[0], cb0);
        if (cb1) atomicAdd(&s_ctb2[1], cb1);
    }
    __syncthreads();
    if (t == 0) { g_bctb[0][b] = s_ctb2[0]; g_bctb[1][b] = s_ctb2[1]; }
}

// Pass 2: metadata only. blkoff scan + newrs + reppos.
__global__ void __launch_bounds__(STPB) k_scan2(int nblocks, int nseg,
                                                float* __restrict__ out,
                                                int off_nr, int osz) {
    __shared__ int wsum[STPB / 32];
    __shared__ int s_carry;
    __shared__ int s_segcnt[MAX_SEG];
    __shared__ int s_argmin[MAX_SEG];
    int t = threadIdx.x, lane = t & 31, w = t >> 5;
    for (int s = t; s < MAX_SEG; s += STPB) { s_segcnt[s] = 0; s_argmin[s] = 0x7fffffff; }
    if (t == 0) s_carry = 0;
    __syncthreads();
    for (int start = 0; start < nblocks; start += STPB) {
        int i = start + t;
        int v = 0;
        if (i < nblocks) {
            int seg0 = g_bseg0[i];
            unsigned m0 = g_bmin[0][i], m1 = g_bmin[1][i];
            int k0 = g_bct[0][i], k1 = g_bct[1][i];
            if (m0 != SENT && m0 == g_segmin[seg0] && __uint_as_float(m0) <= THRESH)
                k0 += g_beq[0][i];
            if (seg0 + 1 < nseg && m1 != SENT && m1 == g_segmin[seg0 + 1] &&
                __uint_as_float(m1) <= THRESH)
                k1 += g_beq[1][i];
            v = k0 + k1;
            if (k0) atomicAdd(&s_segcnt[seg0], k0);
            if (k1 && seg0 + 1 < nseg) atomicAdd(&s_segcnt[seg0 + 1], k1);
            if (m0 != SENT && m0 == g_segmin[seg0])
                atomicMin(&s_argmin[seg0], g_bam[0][i]);
            if (seg0 + 1 < nseg && m1 != SENT && m1 == g_segmin[seg0 + 1])
                atomicMin(&s_argmin[seg0 + 1], g_bam[1][i]);
        }
        int x = v;
#pragma unroll
        for (int o = 1; o < 32; o <<= 1) {
            int y = __shfl_up_sync(~0u, x, o);
            if (lane >= o) x += y;
        }
        if (lane == 31) wsum[w] = x;
        __syncthreads();
        int wbase = 0, total = 0;
#pragma unroll
        for (int j = 0; j < STPB / 32; j++) {
            if (j < w) wbase += wsum[j];
            total += wsum[j];
        }
        int carry = s_carry;
        if (i < nblocks) g_blkoff[i] = carry + wbase + x - v;
        __syncthreads();
        if (t == 0) s_carry = carry + total;
        __syncthreads();
    }
    for (int i = t; i < nblocks; i += STPB) {
        int seg0 = g_bseg0[i];
        unsigned m0 = g_bmin[0][i], m1 = g_bmin[1][i];
        if (m0 != SENT && m0 == g_segmin[seg0] && g_bam[0][i] == s_argmin[seg0])
            g_reppos[seg0] = g_blkoff[i] + g_bctb[0][i];
        if (seg0 + 1 < nseg && m1 != SENT && m1 == g_segmin[seg0 + 1] &&
            g_bam[1][i] == s_argmin[seg0 + 1]) {
            int k0 = g_bct[0][i];
            if (m0 != SENT && m0 == g_segmin[seg0] && __uint_as_float(m0) <= THRESH)
                k0 += g_beq[0][i];
            g_reppos[seg0 + 1] = g_blkoff[i] + k0 + g_bctb[1][i];
        }
    }
    if (t == 0 && off_nr >= 0 && off_nr + nseg < osz) {
        int acc = 0;
        out[off_nr] = 0.0f;
        for (int s = 0; s < nseg; s++) { acc += s_segcnt[s]; out[off_nr + 1 + s] = (float)acc; }
    }
}

// Pass 3: compaction + backgather.
__global__ void __launch_bounds__(TPB) k_write(const float* __restrict__ sc,
                                               int n, int nseg,
                                               float* __restrict__ out,
                                               int off_sel, int cap_sel,
                                               int off_bg, int osz) {
    __shared__ float s_buf[CHUNK];
    __shared__ int s_wt[4][TPB / 32];
    __shared__ int s_off[32];
    int b = blockIdx.x, base = b * CHUNK;
    if (base >= n) return;
    int t = threadIdx.x, lane = t & 31, w = t >> 5;
    int seg0 = g_bseg0[b];
    int b1 = g_rs[seg0 + 1];
    unsigned min0 = g_segmin[seg0];
    unsigned min1 = (seg0 + 1 < nseg) ? g_segmin[seg0 + 1] : SENT;
    int rep0 = g_reppos[seg0];
    int rep1 = (seg0 + 1 < nseg) ? g_reppos[seg0 + 1] : 0;
    bool full = (base + CHUNK <= n);
    bool oneseg = (b1 >= base + CHUNK) || (b1 >= n);

    float v[IPT];
    load_chunk(sc, base, n, t, v, full);

    unsigned km[4];
    int pack = 0;
    if (oneseg) {
#pragma unroll
        for (int j = 0; j < 4; j++) {
            unsigned m = 0;
#pragma unroll
            for (int e = 0; e < 4; e++) {
                float s = v[4 * j + e];
                bool keep = (s > THRESH) || (__float_as_uint(s) == min0);
                m |= ((unsigned)keep) << e;
            }
            km[j] = m;
            pack += __popc(m) << (8 * j);
        }
    } else {
#pragma unroll
        for (int j = 0; j < 4; j++) {
            unsigned m = 0;
#pragma unroll
            for (int e = 0; e < 4; e++) {
                int idx = base + 4 * (j * TPB + t) + e;
                float s = v[4 * j + e];
                bool keep = (s > THRESH) ||
                            (__float_as_uint(s) == ((idx < b1) ? min0 : min1));
                m |= ((unsigned)keep) << e;
            }
            km[j] = m;
            pack += __popc(m) << (8 * j);
        }
    }

    // single packed warp scan (each byte lane <= 128: no carries)
    int x = pack;
#pragma unroll
    for (int o = 1; o < 32; o <<= 1) {
        int y = __shfl_up_sync(~0u, x, o);
        if (lane >= o) x += y;
    }
    int excl = x - pack;
    if (lane == 31) {
#pragma unroll
        for (int j = 0; j < 4; j++) s_wt[j][w] = (x >> (8 * j)) & 255;
    }
    __syncthreads();
    if (t < 32) {
        int val = s_wt[t >> 3][t & 7];    // order (j, w): l = j*8 + w
        int xx = val;
#pragma unroll
        for (int o = 1; o < 32; o <<= 1) {
            int y = __shfl_up_sync(~0u, xx, o);
            if ((t & 31) >= o) xx += y;
        }
        s_off[t] = xx - val;
    }
    __syncthreads();

    int blkoff = g_blkoff[b];
#pragma unroll
    for (int j = 0; j < 4; j++) {
        int pos0 = blkoff + s_off[j * 8 + w] + ((excl >> (8 * j)) & 255);
        float bgv[4];
#pragma unroll
        for (int e = 0; e < 4; e++) {
            int idx = base + 4 * (j * TPB + t) + e;
            bool keep = (km[j] >> e) & 1u;
            int inner = __popc(km[j] & ((1u << e) - 1u));
            int pos = pos0 + inner;
            if (keep && off_sel >= 0 && pos < cap_sel)
                out[off_sel + pos] = (float)idx;
            int rep = (oneseg || idx < b1) ? rep0 : rep1;
            bgv[e] = (float)(keep ? pos : rep);
        }
        float4* sb = reinterpret_cast<float4*>(s_buf);
        sb[j * TPB + t] = make_float4(bgv[0], bgv[1], bgv[2], bgv[3]);
    }
    __syncthreads();

    if (off_bg >= 0) {
        int gbase = off_bg + base;
        if (full) {
            int r0 = (4 - (gbase & 3)) & 3;       // head scalars to reach 16B alignment
            if (t < r0) out[gbase + t] = s_buf[t];
            int body = (CHUNK - r0) >> 2;          // # of aligned float4 stores
            for (int q = t; q < body; q += TPB) {
                int i = r0 + 4 * q;
                float4 f = make_float4(s_buf[i], s_buf[i + 1], s_buf[i + 2], s_buf[i + 3]);
                *reinterpret_cast<float4*>(out + gbase + i) = f;
            }
            int done = r0 + 4 * body;
            if (t < CHUNK - done) out[gbase + done + t] = s_buf[done + t];
        } else {
            int lim = n - base;
            for (int i = t; i < lim; i += TPB) {
                int o2 = gbase + i;
                if (o2 < osz) out[o2] = s_buf[i];
            }
        }
    }
}

extern "C" void kernel_launch(void* const* d_in, const int* in_sizes, int n_in,
                              void* d_out, int out_size) {
    int i_sc = 0;
    for (int i = 1; i < n_in; i++) if (in_sizes[i] > in_sizes[i_sc]) i_sc = i;
    int i_rs = (i_sc == 0 && n_in > 1) ? 1 : 0;
    for (int i = 0; i < n_in; i++)
        if (i != i_sc && in_sizes[i] >= 2 && in_sizes[i] <= MAX_SEG + 1) { i_rs = i; break; }

    const float* sc    = (const float*)d_in[i_sc];
    const int*   rsraw = (const int*)d_in[i_rs];
    int n    = in_sizes[i_sc];
    int nseg = in_sizes[i_rs] - 1;
    if (nseg > MAX_SEG) nseg = MAX_SEG;
    if (nseg < 1) nseg = 1;
    int nblocks = (n + CHUNK - 1) / CHUNK;
    if (nblocks > MAX_BLOCKS) nblocks = MAX_BLOCKS;
    float* out = (float*)d_out;

    int off_sel = -1, cap_sel = 0, off_nr = -1, off_bg = -1;
    if (out_size >= n + nseg + 1) {            // [sel | newrs | backgather]
        cap_sel = out_size - n - (nseg + 1);
        off_sel = 0; off_nr = cap_sel; off_bg = cap_sel + nseg + 1;
    } else if (out_size == nseg + 1) {
        off_nr = 0;
    } else if (out_size == n) {
        off_bg = 0;
    } else {
        off_sel = 0; cap_sel = out_size;
    }

    k_cfg<<<1, 256>>>(rsraw, nseg + 1);
    k_pass1<<<nblocks, TPB>>>(sc, n, nseg);
    k_scan2<<<1, STPB>>>(nblocks, nseg, out, off_nr, out_size);
    k_write<<<nblocks, TPB>>>(sc, n, nseg, out, off_sel, cap_sel, off_bg, out_size);
}

// round 13
// speedup vs baseline: 2.7635x; 1.0640x over previous
#include <cuda_runtime.h>

#define THRESH 0.1f
#define TPB 256
#define IPT 16
#define CHUNK (TPB * IPT)     // 4096
#define STPB 1024
#define MAX_SEG 256
#define MAX_BLOCKS 8192
#define SENT 0xffffffffu
#define PADF __uint_as_float(0xffffffffu)   // -NaN: fails >THRESH, max as uint

// Scratch (no allocations allowed)
__device__ int      g_rs[MAX_SEG + 1];
__device__ unsigned g_segmin[MAX_SEG];
__device__ int      g_reppos[MAX_SEG];
__device__ int      g_blkoff[MAX_BLOCKS];
__device__ int      g_bseg0[MAX_BLOCKS];
__device__ unsigned g_bmin[2][MAX_BLOCKS];
__device__ int      g_bam[2][MAX_BLOCKS];    // first index achieving part min
__device__ int      g_beq[2][MAX_BLOCKS];    // count == part min
__device__ int      g_bct[2][MAX_BLOCKS];    // count > THRESH
__device__ int      g_bctb[2][MAX_BLOCKS];   // count > THRESH with idx < part argmin
__device__ unsigned g_mask[MAX_BLOCKS * TPB];// per-thread 16-bit (s>THRESH) mask

__device__ __forceinline__ int find_seg(int nseg, int i) {
    int lo = 0, hi = nseg;
    while (hi - lo > 1) {
        int mid = (lo + hi) >> 1;
        if (i >= g_rs[mid]) lo = mid; else hi = mid;
    }
    return lo;
}

__global__ void k_cfg(const int* __restrict__ raw, int nrs) {
    int t = threadIdx.x;
    __shared__ int is64;
    if (t == 0)
        is64 = (nrs > 2 && raw[1] == 0 && raw[2] != 0) ? 1 : 0;
    __syncthreads();
    if (t < nrs && t <= MAX_SEG) g_rs[t] = is64 ? raw[2 * t] : raw[t];
    if (t < MAX_SEG) {
        g_segmin[t] = 0x7f800000u;
        g_reppos[t] = 0;
    }
}

// Load CHUNK as interleaved float4: elem e of slot j -> idx = base + 4*(j*TPB+t) + e.
__device__ __forceinline__ void load_chunk(const float* __restrict__ sc,
                                           int base, int n, int t, float* v, bool full) {
    if (full) {
        const float4* p = reinterpret_cast<const float4*>(sc + base);
#pragma unroll
        for (int j = 0; j < 4; j++) {
            float4 f = p[j * TPB + t];
            v[4 * j + 0] = f.x; v[4 * j + 1] = f.y;
            v[4 * j + 2] = f.z; v[4 * j + 3] = f.w;
        }
    } else {
#pragma unroll
        for (int j = 0; j < 4; j++)
#pragma unroll
            for (int e = 0; e < 4; e++) {
                int idx = base + 4 * (j * TPB + t) + e;
                v[4 * j + e] = (idx < n) ? sc[idx] : PADF;
            }
    }
}

// Pass 1: one full read; block-part metadata + per-thread threshold mask.
__global__ void __launch_bounds__(TPB) k_pass1(const float* __restrict__ sc,
                                               int n, int nseg) {
    int b = blockIdx.x, base = b * CHUNK;
    if (base >= n) return;
    int t = threadIdx.x, lane = t & 31, w = t >> 5;
    int seg0 = find_seg(nseg, base);
    int b1 = g_rs[seg0 + 1];
    bool full = (base + CHUNK <= n);
    bool oneseg = (b1 >= base + CHUNK) || (b1 >= n);

    float v[IPT];
    load_chunk(sc, base, n, t, v, full);

    unsigned tmask = 0;
#pragma unroll
    for (int k = 0; k < IPT; k++)
        tmask |= ((unsigned)(v[k] > THRESH)) << k;
    g_mask[b * TPB + t] = tmask;

    if (oneseg) {
        // ---- fast path: single segment ----
        unsigned mn = SENT;
        int ct = __popc(tmask);
#pragma unroll
        for (int k = 0; k < IPT; k++) mn = min(mn, __float_as_uint(v[k]));
        for (int o = 16; o > 0; o >>= 1) {
            mn = min(mn, __shfl_down_sync(~0u, mn, o));
            ct += __shfl_down_sync(~0u, ct, o);
        }
        __shared__ unsigned smn[TPB / 32];
        __shared__ int sct[TPB / 32];
        __shared__ unsigned sM;
        __shared__ int sCt, sEq, sAm, sCtb;
        if (lane == 0) { smn[w] = mn; sct[w] = ct; }
        __syncthreads();
        if (t == 0) {
            unsigned M = smn[0]; int C = sct[0];
#pragma unroll
            for (int i = 1; i < TPB / 32; i++) { M = min(M, smn[i]); C += sct[i]; }
            sM = M; sCt = C; sEq = 0; sAm = 0x7fffffff; sCtb = 0;
        }
        __syncthreads();
        unsigned M = sM;
        int eq = 0, am = 0x7fffffff;
#pragma unroll
        for (int j = 0; j < 4; j++)
#pragma unroll
            for (int e = 0; e < 4; e++) {
                if (__float_as_uint(v[4 * j + e]) == M) {
                    eq++;
                    am = min(am, base + 4 * (j * TPB + t) + e);
                }
            }
        for (int o = 16; o > 0; o >>= 1) {
            eq += __shfl_down_sync(~0u, eq, o);
            am = min(am, __shfl_down_sync(~0u, am, o));
        }
        if (lane == 0 && eq) { atomicAdd(&sEq, eq); atomicMin(&sAm, am); }
        __syncthreads();
        int A = sAm;
        int cb = 0;
#pragma unroll
        for (int j = 0; j < 4; j++)
#pragma unroll
            for (int e = 0; e < 4; e++) {
                int idx = base + 4 * (j * TPB + t) + e;
                cb += (int)((v[4 * j + e] > THRESH) && idx < A);
            }
        for (int o = 16; o > 0; o >>= 1) cb += __shfl_down_sync(~0u, cb, o);
        if (lane == 0 && cb) atomicAdd(&sCtb, cb);
        __syncthreads();
        if (t == 0) {
            g_bmin[0][b] = M; g_beq[0][b] = sEq; g_bam[0][b] = sAm;
            g_bct[0][b] = sCt; g_bctb[0][b] = sCtb;
            g_bmin[1][b] = SENT; g_beq[1][b] = 0; g_bam[1][b] = 0x7fffffff;
            g_bct[1][b] = 0; g_bctb[1][b] = 0;
            g_bseg0[b] = seg0;
            atomicMin(&g_segmin[seg0], M);
        }
        return;
    }

    // ---- slow path: block straddles a segment boundary (rare) ----
    unsigned mn0 = SENT, mn1 = SENT;
    int eq0 = 0, eq1 = 0, am0 = 0x7fffffff, am1 = 0x7fffffff, ct0 = 0, ct1 = 0;
#pragma unroll
    for (int j = 0; j < 4; j++)
#pragma unroll
        for (int e = 0; e < 4; e++) {
            int idx = base + 4 * (j * TPB + t) + e;
            float s = v[4 * j + e];
            unsigned bb = __float_as_uint(s);
            if (idx < b1) {
                ct0 += (int)(s > THRESH);
                if (bb < mn0) { mn0 = bb; eq0 = 1; am0 = idx; }
                else if (bb == mn0) { eq0++; am0 = min(am0, idx); }
            } else {
                ct1 += (int)(s > THRESH);
                if (bb < mn1) { mn1 = bb; eq1 = 1; am1 = idx; }
                else if (bb == mn1) { eq1++; am1 = min(am1, idx); }
            }
        }
    for (int o = 16; o > 0; o >>= 1) {
        unsigned omn0 = __shfl_down_sync(~0u, mn0, o);
        int oeq0 = __shfl_down_sync(~0u, eq0, o);
        int oam0 = __shfl_down_sync(~0u, am0, o);
        int oct0 = __shfl_down_sync(~0u, ct0, o);
        unsigned omn1 = __shfl_down_sync(~0u, mn1, o);
        int oeq1 = __shfl_down_sync(~0u, eq1, o);
        int oam1 = __shfl_down_sync(~0u, am1, o);
        int oct1 = __shfl_down_sync(~0u, ct1, o);
        ct0 += oct0; ct1 += oct1;
        if (omn0 < mn0) { mn0 = omn0; eq0 = oeq0; am0 = oam0; }
        else if (omn0 == mn0 && mn0 != SENT) { eq0 += oeq0; am0 = min(am0, oam0); }
        if (omn1 < mn1) { mn1 = omn1; eq1 = oeq1; am1 = oam1; }
        else if (omn1 == mn1 && mn1 != SENT) { eq1 += oeq1; am1 = min(am1, oam1); }
    }
    __shared__ unsigned smn2[2][TPB / 32];
    __shared__ int seq2[2][TPB / 32], sam2[2][TPB / 32], sct2[2][TPB / 32];
    __shared__ int s_am2[2], s_ctb2[2];
    if (lane == 0) {
        smn2[0][w] = mn0; seq2[0][w] = eq0; sam2[0][w] = am0; sct2[0][w] = ct0;
        smn2[1][w] = mn1; seq2[1][w] = eq1; sam2[1][w] = am1; sct2[1][w] = ct1;
    }
    __syncthreads();
    if (t == 0) {
#pragma unroll
        for (int p = 0; p < 2; p++) {
            unsigned M = smn2[p][0]; int E = seq2[p][0], A = sam2[p][0], C = sct2[p][0];
            for (int i = 1; i < TPB / 32; i++) {
                C += sct2[p][i];
                unsigned m = smn2[p][i];
                if (m < M) { M = m; E = seq2[p][i]; A = sam2[p][i]; }
                else if (m == M && M != SENT) { E += seq2[p][i]; A = min(A, sam2[p][i]); }
            }
            g_bmin[p][b] = M; g_beq[p][b] = E; g_bam[p][b] = A; g_bct[p][b] = C;
            s_am2[p] = A; s_ctb2[p] = 0;
            if (M != SENT) {
                int seg = seg0 + p;
                if (seg < nseg) atomicMin(&g_segmin[seg], M);
            }
        }
        g_bseg0[b] = seg0;
    }
    __syncthreads();
    int A0 = s_am2[0], A1 = s_am2[1];
    int cb0 = 0, cb1 = 0;
#pragma unroll
    for (int j = 0; j < 4; j++)
#pragma unroll
        for (int e = 0; e < 4; e++) {
            int idx = base + 4 * (j * TPB + t) + e;
            bool thr = v[4 * j + e] > THRESH;
            if (idx < b1) cb0 += (int)(thr && idx < A0);
            else          cb1 += (int)(thr && idx < A1);
        }
    for (int o = 16; o > 0; o >>= 1) {
        cb0 += __shfl_down_sync(~0u, cb0, o);
        cb1 += __shfl_down_sync(~0u, cb1, o);
    }
    if (lane == 0) {
        if (cb0) atomicAdd(&s_ctb2[0], cb0);
        if (cb1) atomicAdd(&s_ctb2[1], cb1);
    }
    __syncthreads();
    if (t == 0) { g_bctb[0][b] = s_ctb2[0]; g_bctb[1][b] = s_ctb2[1]; }
}

// Pass 2: metadata only. blkoff scan + newrs + reppos.
__global__ void __launch_bounds__(STPB) k_scan2(int nblocks, int nseg,
                                                float* __restrict__ out,
                                                int off_nr, int osz) {
    __shared__ int wsum[STPB / 32];
    __shared__ int s_carry;
    __shared__ int s_segcnt[MAX_SEG];
    __shared__ int s_argmin[MAX_SEG];
    int t = threadIdx.x, lane = t & 31, w = t >> 5;
    for (int s = t; s < MAX_SEG; s += STPB) { s_segcnt[s] = 0; s_argmin[s] = 0x7fffffff; }
    if (t == 0) s_carry = 0;
    __syncthreads();
    for (int start = 0; start < nblocks; start += STPB) {
        int i = start + t;
        int v = 0;
        if (i < nblocks) {
            int seg0 = g_bseg0[i];
            unsigned m0 = g_bmin[0][i], m1 = g_bmin[1][i];
            int k0 = g_bct[0][i], k1 = g_bct[1][i];
            if (m0 != SENT && m0 == g_segmin[seg0] && __uint_as_float(m0) <= THRESH)
                k0 += g_beq[0][i];
            if (seg0 + 1 < nseg && m1 != SENT && m1 == g_segmin[seg0 + 1] &&
                __uint_as_float(m1) <= THRESH)
                k1 += g_beq[1][i];
            v = k0 + k1;
            if (k0) atomicAdd(&s_segcnt[seg0], k0);
            if (k1 && seg0 + 1 < nseg) atomicAdd(&s_segcnt[seg0 + 1], k1);
            if (m0 != SENT && m0 == g_segmin[seg0])
                atomicMin(&s_argmin[seg0], g_bam[0][i]);
            if (seg0 + 1 < nseg && m1 != SENT && m1 == g_segmin[seg0 + 1])
                atomicMin(&s_argmin[seg0 + 1], g_bam[1][i]);
        }
        int x = v;
#pragma unroll
        for (int o = 1; o < 32; o <<= 1) {
            int y = __shfl_up_sync(~0u, x, o);
            if (lane >= o) x += y;
        }
        if (lane == 31) wsum[w] = x;
        __syncthreads();
        int wbase = 0, total = 0;
#pragma unroll
        for (int j = 0; j < STPB / 32; j++) {
            if (j < w) wbase += wsum[j];
            total += wsum[j];
        }
        int carry = s_carry;
        if (i < nblocks) g_blkoff[i] = carry + wbase + x - v;
        __syncthreads();
        if (t == 0) s_carry = carry + total;
        __syncthreads();
    }
    for (int i = t; i < nblocks; i += STPB) {
        int seg0 = g_bseg0[i];
        unsigned m0 = g_bmin[0][i], m1 = g_bmin[1][i];
        if (m0 != SENT && m0 == g_segmin[seg0] && g_bam[0][i] == s_argmin[seg0])
            g_reppos[seg0] = g_blkoff[i] + g_bctb[0][i];
        if (seg0 + 1 < nseg && m1 != SENT && m1 == g_segmin[seg0 + 1] &&
            g_bam[1][i] == s_argmin[seg0 + 1]) {
            int k0 = g_bct[0][i];
            if (m0 != SENT && m0 == g_segmin[seg0] && __uint_as_float(m0) <= THRESH)
                k0 += g_beq[0][i];
            g_reppos[seg0 + 1] = g_blkoff[i] + k0 + g_bctb[1][i];
        }
    }
    if (t == 0 && off_nr >= 0 && off_nr + nseg < osz) {
        int acc = 0;
        out[off_nr] = 0.0f;
        for (int s = 0; s < nseg; s++) { acc += s_segcnt[s]; out[off_nr + 1 + s] = (float)acc; }
    }
}

// Pass 3: mask-driven compaction + backgather (no score re-read except min blocks).
__global__ void __launch_bounds__(TPB) k_write(const float* __restrict__ sc,
                                               int n, int nseg,
                                               float* __restrict__ out,
                                               int off_sel, int cap_sel,
                                               int off_bg, int osz) {
    __shared__ float s_buf[CHUNK];
    __shared__ int s_wt[4][TPB / 32];
    __shared__ int s_off[32];
    int b = blockIdx.x, base = b * CHUNK;
    if (base >= n) return;
    int t = threadIdx.x, lane = t & 31, w = t >> 5;
    int seg0 = g_bseg0[b];
    int b1 = g_rs[seg0 + 1];
    unsigned min0 = g_segmin[seg0];
    unsigned min1 = (seg0 + 1 < nseg) ? g_segmin[seg0 + 1] : SENT;
    int rep0 = g_reppos[seg0];
    int rep1 = (seg0 + 1 < nseg) ? g_reppos[seg0 + 1] : 0;
    bool full = (base + CHUNK <= n);
    bool oneseg = (b1 >= base + CHUNK) || (b1 >= n);

    unsigned tmask = g_mask[b * TPB + t];

    // rare fix-up: only blocks whose part-min equals segmin (with segmin<=THRESH)
    bool need0 = (g_bmin[0][b] == min0) && (__uint_as_float(min0) <= THRESH);
    bool need1 = (!oneseg) && (seg0 + 1 < nseg) &&
                 (g_bmin[1][b] == min1) && (__uint_as_float(min1) <= THRESH);
    if (need0 || need1) {
        float v[IPT];
        load_chunk(sc, base, n, t, v, full);
#pragma unroll
        for (int j = 0; j < 4; j++)
#pragma unroll
            for (int e = 0; e < 4; e++) {
                int idx = base + 4 * (j * TPB + t) + e;
                unsigned bits = __float_as_uint(v[4 * j + e]);
                bool p0 = oneseg || (idx < b1);
                bool hit = p0 ? (need0 && bits == min0) : (need1 && bits == min1);
                if (hit) tmask |= 1u << (4 * j + e);
            }
    }

    unsigned km[4];
    int pack = 0;
#pragma unroll
    for (int j = 0; j < 4; j++) {
        km[j] = (tmask >> (4 * j)) & 15u;
        pack += __popc(km[j]) << (8 * j);
    }

    // single packed warp scan (byte lanes <= 128: no carries)
    int x = pack;
#pragma unroll
    for (int o = 1; o < 32; o <<= 1) {
        int y = __shfl_up_sync(~0u, x, o);
        if (lane >= o) x += y;
    }
    int excl = x - pack;
    if (lane == 31) {
#pragma unroll
        for (int j = 0; j < 4; j++) s_wt[j][w] = (x >> (8 * j)) & 255;
    }
    __syncthreads();
    if (t < 32) {
        int val = s_wt[t >> 3][t & 7];    // order (j, w): l = j*8 + w
        int xx = val;
#pragma unroll
        for (int o = 1; o < 32; o <<= 1) {
            int y = __shfl_up_sync(~0u, xx, o);
            if ((t & 31) >= o) xx += y;
        }
        s_off[t] = xx - val;
    }
    __syncthreads();

    int blkoff = g_blkoff[b];
#pragma unroll
    for (int j = 0; j < 4; j++) {
        int pos0 = blkoff + s_off[j * 8 + w] + ((excl >> (8 * j)) & 255);
        float bgv[4];
#pragma unroll
        for (int e = 0; e < 4; e++) {
            int idx = base + 4 * (j * TPB + t) + e;
            bool keep = (km[j] >> e) & 1u;
            int inner = __popc(km[j] & ((1u << e) - 1u));
            int pos = pos0 + inner;
            if (keep && off_sel >= 0 && pos < cap_sel)
                out[off_sel + pos] = (float)idx;
            int rep = (oneseg || idx < b1) ? rep0 : rep1;
            bgv[e] = (float)(keep ? pos : rep);
        }
        float4* sb = reinterpret_cast<float4*>(s_buf);
        sb[j * TPB + t] = make_float4(bgv[0], bgv[1], bgv[2], bgv[3]);
    }
    __syncthreads();

    if (off_bg >= 0) {
        int gbase = off_bg + base;
        if (full) {
            int r0 = (4 - (gbase & 3)) & 3;     // head scalars to reach alignment
            const float4* sb4 = reinterpret_cast<const float4*>(s_buf);
            if (r0 == 0) {
                float4* og = reinterpret_cast<float4*>(out + gbase);
                for (int q = t; q < CHUNK / 4; q += TPB) og[q] = sb4[q];
            } else {
                if (t < r0) out[gbase + t] = s_buf[t];
                int nq = (CHUNK - r0) >> 2;      // 1023
                for (int q = t; q < nq; q += TPB) {
                    float4 a = sb4[q];
                    float4 c = sb4[q + 1];       // q <= 1022 -> in range
                    float4 o4;
                    if (r0 == 1)      o4 = make_float4(a.y, a.z, a.w, c.x);
                    else if (r0 == 2) o4 = make_float4(a.z, a.w, c.x, c.y);
                    else              o4 = make_float4(a.w, c.x, c.y, c.z);
                    *reinterpret_cast<float4*>(out + gbase + r0 + 4 * q) = o4;
                }
                int done = r0 + 4 * nq;
                if (t < CHUNK - done) out[gbase + done + t] = s_buf[done + t];
            }
        } else {
            int lim = n - base;
            for (int i = t; i < lim; i += TPB) {
                int o2 = gbase + i;
                if (o2 < osz) out[o2] = s_buf[i];
            }
        }
    }
}

extern "C" void kernel_launch(void* const* d_in, const int* in_sizes, int n_in,
                              void* d_out, int out_size) {
    int i_sc = 0;
    for (int i = 1; i < n_in; i++) if (in_sizes[i] > in_sizes[i_sc]) i_sc = i;
    int i_rs = (i_sc == 0 && n_in > 1) ? 1 : 0;
    for (int i = 0; i < n_in; i++)
        if (i != i_sc && in_sizes[i] >= 2 && in_sizes[i] <= MAX_SEG + 1) { i_rs = i; break; }

    const float* sc    = (const float*)d_in[i_sc];
    const int*   rsraw = (const int*)d_in[i_rs];
    int n    = in_sizes[i_sc];
    int nseg = in_sizes[i_rs] - 1;
    if (nseg > MAX_SEG) nseg = MAX_SEG;
    if (nseg < 1) nseg = 1;
    int nblocks = (n + CHUNK - 1) / CHUNK;
    if (nblocks > MAX_BLOCKS) nblocks = MAX_BLOCKS;
    float* out = (float*)d_out;

    int off_sel = -1, cap_sel = 0, off_nr = -1, off_bg = -1;
    if (out_size >= n + nseg + 1) {            // [sel | newrs | backgather]
        cap_sel = out_size - n - (nseg + 1);
        off_sel = 0; off_nr = cap_sel; off_bg = cap_sel + nseg + 1;
    } else if (out_size == nseg + 1) {
        off_nr = 0;
    } else if (out_size == n) {
        off_bg = 0;
    } else {
        off_sel = 0; cap_sel = out_size;
    }

    k_cfg<<<1, 256>>>(rsraw, nseg + 1);
    k_pass1<<<nblocks, TPB>>>(sc, n, nseg);
    k_scan2<<<1, STPB>>>(nblocks, nseg, out, off_nr, out_size);
    k_write<<<nblocks, TPB>>>(sc, n, nseg, out, off_sel, cap_sel, off_bg, out_size);
}